// round 15
// baseline (speedup 1.0000x reference)
#include <cuda_runtime.h>
#include <cuda.h>
#include <cuda_fp16.h>
#include <math.h>
#include <stdint.h>

// Problem constants
#define NUM_HEADS 16
#define HEAD_SIZE 128
#define HIDDEN    2048
#define ROT       16
#define BATCH     4
#define SEQ       1024
#define TOTAL     4096
#define QKV_N     6144

// -------- device scratch --------
__device__ __half g_qh[(size_t)TOTAL * HIDDEN];        // Q half, pre-scaled, [B,H,S,D]
__device__ __half g_kh[(size_t)TOTAL * HIDDEN];        // K half, [B,H,S,D]
__device__ __half g_vh[(size_t)TOTAL * HIDDEN];        // V half, [B,H,S,D]
__device__ __half g_attnh[(size_t)TOTAL * HIDDEN];     // flash output (half)
__device__ __half g_hidh[(size_t)TOTAL * HIDDEN];      // hidden states (half)
__device__ __half g_wqkvh[(size_t)HIDDEN * QKV_N];     // W_qkv [K][N] half (orig layout)
__device__ __half g_wdenseh[(size_t)HIDDEN * HIDDEN];  // W_dense [K][N] half

// ============================================================================
// helpers
// ============================================================================
__device__ __forceinline__ uint32_t smem_u32(const void* p) {
    uint32_t a;
    asm("{ .reg .u64 t; cvta.to.shared.u64 t, %1; cvt.u32.u64 %0, t; }" : "=r"(a) : "l"(p));
    return a;
}
__device__ __forceinline__ void mma_f16(float* c, const uint32_t* a, uint32_t b0, uint32_t b1) {
    asm volatile(
        "mma.sync.aligned.m16n8k16.row.col.f32.f16.f16.f32 "
        "{%0,%1,%2,%3}, {%4,%5,%6,%7}, {%8,%9}, {%0,%1,%2,%3};"
        : "+f"(c[0]), "+f"(c[1]), "+f"(c[2]), "+f"(c[3])
        : "r"(a[0]), "r"(a[1]), "r"(a[2]), "r"(a[3]), "r"(b0), "r"(b1));
}
__device__ __forceinline__ void ldsm_x4(uint32_t* r, uint32_t addr) {
    asm volatile("ldmatrix.sync.aligned.m8n8.x4.shared.b16 {%0,%1,%2,%3}, [%4];"
        : "=r"(r[0]), "=r"(r[1]), "=r"(r[2]), "=r"(r[3]) : "r"(addr));
}
__device__ __forceinline__ void ldsm_x4_t(uint32_t* r, uint32_t addr) {
    asm volatile("ldmatrix.sync.aligned.m8n8.x4.trans.shared.b16 {%0,%1,%2,%3}, [%4];"
        : "=r"(r[0]), "=r"(r[1]), "=r"(r[2]), "=r"(r[3]) : "r"(addr));
}
__device__ __forceinline__ uint32_t pack_h2(float a, float b) {
    __half2 h = __floats2half2_rn(a, b);
    return *(uint32_t*)&h;
}

// ============================================================================
// GEMM config (unchanged from round-13 validated version)
// ============================================================================
#define NSTAGE 3
#define KCH 64
#define LDH 72
#define LDB 136
#define STAGE_A_B (128 * LDH * 2)      // 18432 B
#define STAGE_B_B (64 * LDB * 2)       // 17408 B
#define GEMM_SMEM_BYTES (NSTAGE * (STAGE_A_B + STAGE_B_B))   // 107520 B

#define GEMM_MAINLOOP(Aptr, Wptr, Kdim, Ndim)                                    \
    extern __shared__ __half hsm[];                                             \
    __half* As = hsm;                                                           \
    __half* Bs = hsm + NSTAGE * (STAGE_A_B / 2);                                \
    const int tid  = threadIdx.x;                                               \
    const int wid  = tid >> 5;                                                  \
    const int lane = tid & 31;                                                  \
    const int wm = wid >> 2;                                                    \
    const int wn = wid & 3;                                                     \
    const int qr = lane >> 2;                                                   \
    const int qc = lane & 3;                                                    \
    const int m0 = blockIdx.y * 128;                                            \
    const int n0 = blockIdx.x * 128;                                            \
    const int lrow = lane & 15;                                                 \
    const int lcol = (lane >> 4) * 8;                                           \
    const int rowA = tid >> 3;                                                  \
    const int cA   = (tid & 7) << 3;                                            \
    const int rowB = tid >> 4;                                                  \
    const int cB   = (tid & 15) << 3;                                           \
    const __half* srcA = (Aptr) + (size_t)(m0 + rowA) * (Kdim) + cA;            \
    const __half* srcB = (Wptr) + (size_t)rowB * (Ndim) + n0 + cB;              \
    const uint32_t dA0 = smem_u32(As) + (uint32_t)(rowA * LDH + cA) * 2u;       \
    const uint32_t dB0 = smem_u32(Bs) + (uint32_t)(rowB * LDB + cB) * 2u;       \
    const size_t gRowA = (size_t)32 * (Kdim);                                   \
    const size_t gRowB = (size_t)16 * (Ndim);                                   \
    const uint32_t sRowA = 32u * LDH * 2u;                                      \
    const uint32_t sRowB = 16u * LDB * 2u;                                      \
    uint32_t aAddr[4], bAddr[2];                                                \
    _Pragma("unroll")                                                           \
    for (int mt = 0; mt < 4; ++mt)                                              \
        aAddr[mt] = smem_u32(As) + (uint32_t)((wm * 64 + mt * 16 + lrow) * LDH + lcol) * 2u; \
    _Pragma("unroll")                                                           \
    for (int g = 0; g < 2; ++g)                                                 \
        bAddr[g] = smem_u32(Bs) + (uint32_t)(lrow * LDB + wn * 32 + g * 16 + lcol) * 2u; \
    float acc[4][4][4];                                                         \
    _Pragma("unroll")                                                           \
    for (int i = 0; i < 4; ++i)                                                 \
        _Pragma("unroll")                                                       \
        for (int j = 0; j < 4; ++j)                                             \
            _Pragma("unroll")                                                   \
            for (int k = 0; k < 4; ++k) acc[i][j][k] = 0.0f;                    \
    auto load_chunk = [&](const __half* pA, const __half* pB, int si) {         \
        const uint32_t oA = (uint32_t)si * STAGE_A_B;                           \
        const uint32_t oB = (uint32_t)si * STAGE_B_B;                           \
        _Pragma("unroll")                                                       \
        for (int it = 0; it < 4; ++it) {                                        \
            asm volatile("cp.async.cg.shared.global [%0], [%1], 16;"            \
                :: "r"(dA0 + oA + it * sRowA), "l"(pA + it * gRowA) : "memory");\
            asm volatile("cp.async.cg.shared.global [%0], [%1], 16;"            \
                :: "r"(dB0 + oB + it * sRowB), "l"(pB + it * gRowB) : "memory");\
        }                                                                       \
        asm volatile("cp.async.commit_group;" ::: "memory");                    \
    };                                                                          \
    const int NCH = (Kdim) / KCH;                                               \
    load_chunk(srcA, srcB, 0);                                                  \
    srcA += KCH; srcB += (size_t)KCH * (Ndim);                                  \
    load_chunk(srcA, srcB, 1);                                                  \
    srcA += KCH; srcB += (size_t)KCH * (Ndim);                                  \
    int sCi = 0, sLi = 2;                                                       \
    for (int c = 0; c < NCH; ++c) {                                             \
        if (c + 1 < NCH) { asm volatile("cp.async.wait_group 1;" ::: "memory"); }\
        else             { asm volatile("cp.async.wait_group 0;" ::: "memory"); }\
        __syncthreads();                                                        \
        if (c + 2 < NCH) {                                                      \
            load_chunk(srcA, srcB, sLi);                                        \
            srcA += KCH; srcB += (size_t)KCH * (Ndim);                          \
            if (++sLi == NSTAGE) sLi = 0;                                       \
        }                                                                       \
        _Pragma("unroll")                                                       \
        for (int ks = 0; ks < 4; ++ks) {                                        \
            const uint32_t kOffA = (uint32_t)sCi * STAGE_A_B + (uint32_t)(ks * 32); \
            const uint32_t kOffB = (uint32_t)sCi * STAGE_B_B + (uint32_t)(ks * 16) * LDB * 2u; \
            uint32_t af[4][4];                                                  \
            _Pragma("unroll")                                                   \
            for (int mt = 0; mt < 4; ++mt)                                      \
                ldsm_x4(af[mt], aAddr[mt] + kOffA);                             \
            uint32_t bf[2][4];                                                  \
            _Pragma("unroll")                                                   \
            for (int g = 0; g < 2; ++g)                                         \
                ldsm_x4_t(bf[g], bAddr[g] + kOffB);                             \
            _Pragma("unroll")                                                   \
            for (int mt = 0; mt < 4; ++mt)                                      \
                _Pragma("unroll")                                               \
                for (int g = 0; g < 2; ++g) {                                   \
                    mma_f16(acc[mt][2 * g    ], af[mt], bf[g][0], bf[g][1]);    \
                    mma_f16(acc[mt][2 * g + 1], af[mt], bf[g][2], bf[g][3]);    \
                }                                                               \
        }                                                                       \
        if (++sCi == NSTAGE) sCi = 0;                                           \
    }

// ============================================================================
// Kernel A: QKV GEMM with FUSED bias + RoPE + split epilogue. (unchanged)
// ============================================================================
__global__ void __launch_bounds__(256, 2) gemm_qkv_rope(
    const __half* __restrict__ A, const __half* __restrict__ W,
    const float* __restrict__ bias,
    const float* __restrict__ cosb, const float* __restrict__ sinb)
{
    GEMM_MAINLOOP(A, W, HIDDEN, QKV_N)

    const int col0 = n0 + wn * 32;
    const int which = col0 >> 11;              // 0=q, 1=k, 2=v
    const int hd = (col0 & 2047) >> 7;
    const int d0 = col0 & 127;
    __half* outBase = (which == 0) ? g_qh : (which == 1) ? g_kh : g_vh;
    const bool ropez = (d0 == 0) && (which < 2);
    const float qs = (which == 0) ? 0.08838834764831845f : 1.0f;

#pragma unroll
    for (int mt = 0; mt < 4; ++mt) {
        const int t0 = m0 + wm * 64 + mt * 16 + qr;
        const int t1 = t0 + 8;

        float vals[4][4];
#pragma unroll
        for (int nt = 0; nt < 4; ++nt) {
            const int col = col0 + nt * 8 + 2 * qc;
            const float2 bv = *(const float2*)&bias[col];
            vals[nt][0] = acc[mt][nt][0] + bv.x;
            vals[nt][1] = acc[mt][nt][1] + bv.y;
            vals[nt][2] = acc[mt][nt][2] + bv.x;
            vals[nt][3] = acc[mt][nt][3] + bv.y;
        }

        if (ropez) {
#pragma unroll
            for (int nt = 0; nt < 2; ++nt) {
                const int r = nt * 8 + 2 * qc;
                const float c0a = cosb[t0 * ROT + r],     s0a = sinb[t0 * ROT + r];
                const float c0b = cosb[t0 * ROT + r + 1], s0b = sinb[t0 * ROT + r + 1];
                const float c1a = cosb[t1 * ROT + r],     s1a = sinb[t1 * ROT + r];
                const float c1b = cosb[t1 * ROT + r + 1], s1b = sinb[t1 * ROT + r + 1];
                float x1, x2;
                x1 = vals[nt][0]; x2 = vals[nt + 2][0];
                vals[nt][0] = x1 * c0a - x2 * s0a; vals[nt + 2][0] = x1 * s0a + x2 * c0a;
                x1 = vals[nt][1]; x2 = vals[nt + 2][1];
                vals[nt][1] = x1 * c0b - x2 * s0b; vals[nt + 2][1] = x1 * s0b + x2 * c0b;
                x1 = vals[nt][2]; x2 = vals[nt + 2][2];
                vals[nt][2] = x1 * c1a - x2 * s1a; vals[nt + 2][2] = x1 * s1a + x2 * c1a;
                x1 = vals[nt][3]; x2 = vals[nt + 2][3];
                vals[nt][3] = x1 * c1b - x2 * s1b; vals[nt + 2][3] = x1 * s1b + x2 * c1b;
            }
        }

        const int b0i = t0 >> 10, s0i = t0 & 1023;
        const int b1i = t1 >> 10, s1i = t1 & 1023;
        const size_t base0 = ((size_t)(b0i * NUM_HEADS + hd) * SEQ + s0i) * HEAD_SIZE;
        const size_t base1 = ((size_t)(b1i * NUM_HEADS + hd) * SEQ + s1i) * HEAD_SIZE;
#pragma unroll
        for (int nt = 0; nt < 4; ++nt) {
            const int d = d0 + nt * 8 + 2 * qc;
            *(__half2*)&outBase[base0 + d] =
                __floats2half2_rn(vals[nt][0] * qs, vals[nt][1] * qs);
            *(__half2*)&outBase[base1 + d] =
                __floats2half2_rn(vals[nt][2] * qs, vals[nt][3] * qs);
        }
    }
}

// ============================================================================
// Kernel B: dense GEMM (fp32 output + bias) (unchanged)
// ============================================================================
__global__ void __launch_bounds__(256, 2) gemm_dense(
    const __half* __restrict__ A, const __half* __restrict__ W,
    const float* __restrict__ bias, float* __restrict__ Cf)
{
    GEMM_MAINLOOP(A, W, HIDDEN, HIDDEN)

#pragma unroll
    for (int mt = 0; mt < 4; ++mt) {
        const int row = m0 + wm * 64 + mt * 16 + qr;
#pragma unroll
        for (int nt = 0; nt < 4; ++nt) {
            const int col = n0 + wn * 32 + nt * 8 + 2 * qc;
            const float2 bv = *(const float2*)&bias[col];
            *(float2*)&Cf[(size_t)row * HIDDEN + col] =
                make_float2(acc[mt][nt][0] + bv.x, acc[mt][nt][1] + bv.y);
            *(float2*)&Cf[(size_t)(row + 8) * HIDDEN + col] =
                make_float2(acc[mt][nt][2] + bv.x, acc[mt][nt][3] + bv.y);
        }
    }
}

// ============================================================================
// Merged f2h prep (unchanged)
// ============================================================================
#define N4_HID   (TOTAL * HIDDEN / 4)
#define N4_WQKV  (HIDDEN * QKV_N / 4)
#define N4_WD    (HIDDEN * HIDDEN / 4)
#define N4_ALL   (N4_HID + N4_WQKV + N4_WD)

__global__ void __launch_bounds__(256) f2h_all(
    const float* __restrict__ hid, const float* __restrict__ wqkv,
    const float* __restrict__ wd)
{
    const int i = blockIdx.x * 256 + threadIdx.x;
    if (i >= N4_ALL) return;
    const float* src;
    __half* dst;
    int j;
    if (i < N4_HID)              { src = hid;  dst = g_hidh;    j = i; }
    else if (i < N4_HID + N4_WQKV) { src = wqkv; dst = g_wqkvh; j = i - N4_HID; }
    else                         { src = wd;   dst = g_wdenseh; j = i - N4_HID - N4_WQKV; }
    float4 v = ((const float4*)src)[j];
    ((__half2*)dst)[2 * j]     = __floats2half2_rn(v.x, v.y);
    ((__half2*)dst)[2 * j + 1] = __floats2half2_rn(v.z, v.w);
}

// ============================================================================
// flash attention v8 — FQT=128, HEAVY-FIRST scheduling, 3-stage K/V ring with
// a single barrier per k-tile (stage written at kt+2 was consumed at kt-1;
// the iter-kt barrier orders the reuse — same proof as the GEMM pipeline).
// ============================================================================
#define FQT 128
#define FKT 64
#define LDK 136
#define FSTAGE 3
#define KV_STAGE_B (FKT * LDK * 2)      // 17408 B per matrix per stage

struct Flash8Smem {
    __half Qs[FQT][LDK];                   // 34816 B
    __half Ks[FSTAGE][FKT][LDK];           // 52224 B
    __half Vs[FSTAGE][FKT][LDK];           // 52224 B
};                                          // 139264 B

__global__ void __launch_bounds__(256) flash_f16_v8()
{
    extern __shared__ char sraw[];
    Flash8Smem& S = *reinterpret_cast<Flash8Smem*>(sraw);

    // heavy-first: high-qt CTAs (most k-tiles) are scheduled first
    const int qt = (int)(gridDim.x - 1 - blockIdx.x);
    const int h  = blockIdx.y;
    const int b  = blockIdx.z;
    const int tid  = threadIdx.x;
    const int wid  = tid >> 5;
    const int lane = tid & 31;
    const int qr = lane >> 2;
    const int qc = lane & 3;
    const int lrow = lane & 15;
    const int lcol = (lane >> 4) * 8;
    const int m0 = wid * 16;
    const int bh = b * NUM_HEADS + h;
    const size_t headbase = (size_t)bh * SEQ * HEAD_SIZE;

    // ---- load Q tile ----
    {
        const __half* qg = g_qh + headbase + (size_t)(qt * FQT) * HEAD_SIZE;
#pragma unroll
        for (int it = 0; it < 8; ++it) {
            const int flat = it * 256 + tid;
            const int r = flat >> 4;
            const int c = (flat & 15) << 3;
            *(uint4*)&S.Qs[r][c] = *(const uint4*)(qg + (size_t)r * HEAD_SIZE + c);
        }
    }

    auto issue_tile = [&](int kt, int buf) {
        const __half* kg = g_kh + headbase + (size_t)(kt * FKT) * HEAD_SIZE;
        const __half* vg = g_vh + headbase + (size_t)(kt * FKT) * HEAD_SIZE;
        const uint32_t kd = smem_u32(&S.Ks[buf][0][0]);
        const uint32_t vd = smem_u32(&S.Vs[buf][0][0]);
#pragma unroll
        for (int it = 0; it < 4; ++it) {
            const int flat = it * 256 + tid;
            const int r = flat >> 4;
            const int c = (flat & 15) << 3;
            const uint32_t so = (uint32_t)(r * LDK + c) * 2u;
            const size_t go = (size_t)r * HEAD_SIZE + c;
            asm volatile("cp.async.cg.shared.global [%0], [%1], 16;"
                :: "r"(kd + so), "l"(kg + go) : "memory");
            asm volatile("cp.async.cg.shared.global [%0], [%1], 16;"
                :: "r"(vd + so), "l"(vg + go) : "memory");
        }
        asm volatile("cp.async.commit_group;" ::: "memory");
    };

    const int nkt = 2 * qt + 2;
    issue_tile(0, 0);
    if (nkt > 1) issue_tile(1, 1);
    __syncthreads();   // Q smem stores visible to all warps

    uint32_t qf[8][4];
#pragma unroll
    for (int ks = 0; ks < 8; ++ks)
        ldsm_x4(qf[ks], smem_u32(&S.Qs[m0 + lrow][ks * 16 + lcol]));

    float m0r = -1e30f, m1r = -1e30f, l0r = 0.0f, l1r = 0.0f;
    float oacc[16][4];
#pragma unroll
    for (int i = 0; i < 16; ++i)
#pragma unroll
        for (int j = 0; j < 4; ++j) oacc[i][j] = 0.0f;

    int sCi = 0, sLi = 2;
    for (int kt = 0; kt < nkt; ++kt) {
        if (kt + 1 < nkt) { asm volatile("cp.async.wait_group 1;" ::: "memory"); }
        else              { asm volatile("cp.async.wait_group 0;" ::: "memory"); }
        __syncthreads();   // single barrier: tile kt visible AND stage sLi free

        if (kt + 2 < nkt) {
            issue_tile(kt + 2, sLi);
            if (++sLi == FSTAGE) sLi = 0;
        }

        // ---- score: S[16x64] per warp ----
        float sacc[8][4];
#pragma unroll
        for (int i = 0; i < 8; ++i)
#pragma unroll
            for (int j = 0; j < 4; ++j) sacc[i][j] = 0.0f;
        {
            const uint32_t kBase = smem_u32(&S.Ks[sCi][lrow][lcol]);
#pragma unroll
            for (int ks = 0; ks < 8; ++ks) {
#pragma unroll
                for (int nt2 = 0; nt2 < 4; ++nt2) {
                    uint32_t bf[4];
                    ldsm_x4(bf, kBase + (uint32_t)(nt2 * 16 * LDK * 2 + ks * 32));
                    mma_f16(sacc[2 * nt2    ], qf[ks], bf[0], bf[2]);
                    mma_f16(sacc[2 * nt2 + 1], qf[ks], bf[1], bf[3]);
                }
            }
        }

        // ---- causal mask (last two k-tiles only) ----
        if (kt >= 2 * qt) {
            const int moff = (kt - 2 * qt) * 64;
            const int lr0 = m0 + qr;
            const int lr1 = m0 + qr + 8;
#pragma unroll
            for (int nt = 0; nt < 8; ++nt) {
                const int lc = moff + nt * 8 + 2 * qc;
                if (lc     > lr0) sacc[nt][0] = -1e30f;
                if (lc + 1 > lr0) sacc[nt][1] = -1e30f;
                if (lc     > lr1) sacc[nt][2] = -1e30f;
                if (lc + 1 > lr1) sacc[nt][3] = -1e30f;
            }
        }

        // ---- in-register online softmax ----
        float mx0 = -1e30f, mx1 = -1e30f;
#pragma unroll
        for (int nt = 0; nt < 8; ++nt) {
            mx0 = fmaxf(mx0, fmaxf(sacc[nt][0], sacc[nt][1]));
            mx1 = fmaxf(mx1, fmaxf(sacc[nt][2], sacc[nt][3]));
        }
        mx0 = fmaxf(mx0, __shfl_xor_sync(0xffffffffu, mx0, 1));
        mx0 = fmaxf(mx0, __shfl_xor_sync(0xffffffffu, mx0, 2));
        mx1 = fmaxf(mx1, __shfl_xor_sync(0xffffffffu, mx1, 1));
        mx1 = fmaxf(mx1, __shfl_xor_sync(0xffffffffu, mx1, 2));

        const float mn0 = fmaxf(m0r, mx0);
        const float mn1 = fmaxf(m1r, mx1);
        const float a0 = __expf(m0r - mn0);
        const float a1 = __expf(m1r - mn1);
        m0r = mn0; m1r = mn1;

        float s0 = 0.0f, s1 = 0.0f;
        uint32_t pf[4][4];
#pragma unroll
        for (int k2 = 0; k2 < 4; ++k2) {
            const float pa0 = __expf(sacc[2 * k2][0] - mn0);
            const float pa1 = __expf(sacc[2 * k2][1] - mn0);
            const float pb0 = __expf(sacc[2 * k2][2] - mn1);
            const float pb1 = __expf(sacc[2 * k2][3] - mn1);
            const float pc0 = __expf(sacc[2 * k2 + 1][0] - mn0);
            const float pc1 = __expf(sacc[2 * k2 + 1][1] - mn0);
            const float pd0 = __expf(sacc[2 * k2 + 1][2] - mn1);
            const float pd1 = __expf(sacc[2 * k2 + 1][3] - mn1);
            s0 += pa0 + pa1 + pc0 + pc1;
            s1 += pb0 + pb1 + pd0 + pd1;
            pf[k2][0] = pack_h2(pa0, pa1);
            pf[k2][1] = pack_h2(pb0, pb1);
            pf[k2][2] = pack_h2(pc0, pc1);
            pf[k2][3] = pack_h2(pd0, pd1);
        }
        s0 += __shfl_xor_sync(0xffffffffu, s0, 1);
        s0 += __shfl_xor_sync(0xffffffffu, s0, 2);
        s1 += __shfl_xor_sync(0xffffffffu, s1, 1);
        s1 += __shfl_xor_sync(0xffffffffu, s1, 2);
        l0r = l0r * a0 + s0;
        l1r = l1r * a1 + s1;

        // ---- rescale + PV via trans-LDSM from V [s][d] ----
#pragma unroll
        for (int nt = 0; nt < 16; ++nt) {
            oacc[nt][0] *= a0; oacc[nt][1] *= a0;
            oacc[nt][2] *= a1; oacc[nt][3] *= a1;
        }
        {
            const uint32_t vBase = smem_u32(&S.Vs[sCi][lrow][lcol]);
#pragma unroll
            for (int k2 = 0; k2 < 4; ++k2) {
                const uint32_t kOff = (uint32_t)(k2 * 16 * LDK * 2);
#pragma unroll
                for (int nt2 = 0; nt2 < 8; ++nt2) {
                    uint32_t bf[4];
                    ldsm_x4_t(bf, vBase + kOff + (uint32_t)(nt2 * 16 * 2));
                    mma_f16(oacc[2 * nt2    ], pf[k2], bf[0], bf[1]);
                    mma_f16(oacc[2 * nt2 + 1], pf[k2], bf[2], bf[3]);
                }
            }
        }
        if (++sCi == FSTAGE) sCi = 0;
    }

    // ---- epilogue ----
    {
        const int t0 = b * SEQ + qt * FQT;
        const float inv0 = 1.0f / l0r;
        const float inv1 = 1.0f / l1r;
        const int row0 = t0 + m0 + qr;
#pragma unroll
        for (int nt = 0; nt < 16; ++nt) {
            const int col = h * HEAD_SIZE + nt * 8 + 2 * qc;
            *(__half2*)&g_attnh[(size_t)row0 * HIDDEN + col] =
                __floats2half2_rn(oacc[nt][0] * inv0, oacc[nt][1] * inv0);
            *(__half2*)&g_attnh[(size_t)(row0 + 8) * HIDDEN + col] =
                __floats2half2_rn(oacc[nt][2] * inv1, oacc[nt][3] * inv1);
        }
    }
}

// ============================================================================
// launch
// ============================================================================
extern "C" void kernel_launch(void* const* d_in, const int* in_sizes, int n_in,
                              void* d_out, int out_size)
{
    const float* hidden  = (const float*)d_in[0];
    const float* cosb    = (const float*)d_in[1];
    const float* sinb    = (const float*)d_in[2];
    const float* W_qkv   = (const float*)d_in[3];
    const float* b_qkv   = (const float*)d_in[4];
    const float* W_dense = (const float*)d_in[5];
    const float* b_dense = (const float*)d_in[6];
    float* out = (float*)d_out;

    __half *attnh_ptr, *hidh_ptr, *wqkvh_ptr, *wdenseh_ptr;
    cudaGetSymbolAddress((void**)&attnh_ptr, g_attnh);
    cudaGetSymbolAddress((void**)&hidh_ptr, g_hidh);
    cudaGetSymbolAddress((void**)&wqkvh_ptr, g_wqkvh);
    cudaGetSymbolAddress((void**)&wdenseh_ptr, g_wdenseh);

    cudaFuncSetAttribute(flash_f16_v8, cudaFuncAttributeMaxDynamicSharedMemorySize,
                         (int)sizeof(Flash8Smem));
    cudaFuncSetAttribute(gemm_qkv_rope, cudaFuncAttributeMaxDynamicSharedMemorySize,
                         GEMM_SMEM_BYTES);
    cudaFuncSetAttribute(gemm_dense, cudaFuncAttributeMaxDynamicSharedMemorySize,
                         GEMM_SMEM_BYTES);

    // 0) operand prep: one merged f2h launch
    f2h_all<<<(N4_ALL + 255) / 256, 256>>>(hidden, W_qkv, W_dense);
    // 1) QKV projection with fused bias+RoPE+split epilogue
    gemm_qkv_rope<<<dim3(QKV_N / 128, TOTAL / 128), 256, GEMM_SMEM_BYTES>>>(
        hidh_ptr, wqkvh_ptr, b_qkv, cosb, sinb);
    // 2) causal flash attention v8 (heavy-first, single-barrier 3-stage)
    flash_f16_v8<<<dim3(SEQ / FQT, NUM_HEADS, BATCH), 256, sizeof(Flash8Smem)>>>();
    // 3) dense projection (fp32 output)
    gemm_dense<<<dim3(HIDDEN / 128, TOTAL / 128), 256, GEMM_SMEM_BYTES>>>(
        attnh_ptr, wdenseh_ptr, b_dense, out);
}